// round 1
// baseline (speedup 1.0000x reference)
#include <cuda_runtime.h>
#include <cuda_fp16.h>
#include <cstdint>

// Problem constants
static constexpr int B_  = 8;
static constexpr int L_  = 8192;
static constexpr int S_  = 512;
static constexpr int DQ_ = 256;
static constexpr int DC_ = 768;
static constexpr int H_  = 8;
static constexpr int DH_ = 64;
static constexpr int IN_ = 512;   // H*DH
static constexpr int LOG2L = 13;  // log2(L_)

// ---------------- static device scratch (no allocations allowed) ----------------
__device__ __half g_Wq[DQ_ * IN_];
__device__ __half g_Wk[DC_ * IN_];
__device__ __half g_Wv[DC_ * IN_];
__device__ __half g_Wo[IN_ * DQ_];
__device__ __half g_q[(size_t)B_ * L_ * IN_];
__device__ __half g_k[(size_t)B_ * S_ * IN_];
__device__ __half g_v[(size_t)B_ * S_ * IN_];
__device__ __half g_o[(size_t)B_ * L_ * IN_];

// ---------------- small helpers ----------------
__device__ __forceinline__ uint32_t smem_u32(const void* p) {
    return (uint32_t)__cvta_generic_to_shared(p);
}
__device__ __forceinline__ void ldsm_x4(uint32_t* r, const void* p) {
    uint32_t a = smem_u32(p);
    asm volatile("ldmatrix.sync.aligned.m8n8.x4.shared.b16 {%0,%1,%2,%3}, [%4];"
                 : "=r"(r[0]), "=r"(r[1]), "=r"(r[2]), "=r"(r[3]) : "r"(a));
}
__device__ __forceinline__ void ldsm_x2(uint32_t* r, const void* p) {
    uint32_t a = smem_u32(p);
    asm volatile("ldmatrix.sync.aligned.m8n8.x2.shared.b16 {%0,%1}, [%2];"
                 : "=r"(r[0]), "=r"(r[1]) : "r"(a));
}
__device__ __forceinline__ void ldsm_x2_t(uint32_t* r, const void* p) {
    uint32_t a = smem_u32(p);
    asm volatile("ldmatrix.sync.aligned.m8n8.x2.trans.shared.b16 {%0,%1}, [%2];"
                 : "=r"(r[0]), "=r"(r[1]) : "r"(a));
}
__device__ __forceinline__ void mma16816(float* c, const uint32_t* a, const uint32_t* b) {
    asm volatile(
        "mma.sync.aligned.m16n8k16.row.col.f32.f16.f16.f32 "
        "{%0,%1,%2,%3}, {%4,%5,%6,%7}, {%8,%9}, {%0,%1,%2,%3};"
        : "+f"(c[0]), "+f"(c[1]), "+f"(c[2]), "+f"(c[3])
        : "r"(a[0]), "r"(a[1]), "r"(a[2]), "r"(a[3]), "r"(b[0]), "r"(b[1]));
}
__device__ __forceinline__ uint32_t h2_as_u32(__half2 h) {
    return *reinterpret_cast<uint32_t*>(&h);
}

// ---------------- weight conversion ----------------
__global__ void f2h_kernel(const float* __restrict__ src, __half* __restrict__ dst, int n) {
    int i = blockIdx.x * 256 + threadIdx.x;
    if (i < n) dst[i] = __float2half_rn(src[i]);
}

// ---------------- generic tiled GEMM: C[M,N] = A[M,K] @ B[K,N] -------------
// A: f32 (converted on load) or f16. B: f16 weights. C: f16 or f32(+bias, seq gate).
// BM=128, BN=128, BK=32, 256 threads = 8 warps (4 m x 2 n), warp tile 32x64.
template <bool A_F32, bool C_F32, bool GATE_SKIP, bool GATE_ZERO, bool BIAS>
__global__ void __launch_bounds__(256)
gemm_mma(const void* __restrict__ Av, const __half* __restrict__ Bw, void* __restrict__ Cv,
         int M, int N, int K, const int* __restrict__ seq, const float* __restrict__ bias) {
    const int bn = blockIdx.x, bm = blockIdx.y;
    const int t = threadIdx.x, lane = t & 31, w = t >> 5;
    const int wm = w & 3, wn = w >> 2;

    if (GATE_SKIP) {
        int r0 = bm * 128;
        if ((r0 & (L_ - 1)) >= seq[r0 >> LOG2L]) return;
    }
    int slen_blk = 0;
    if (GATE_ZERO) {
        int r0 = bm * 128;
        slen_blk = seq[r0 >> LOG2L];
        if ((r0 & (L_ - 1)) >= slen_blk) {
            // entire tile invalid: write zeros
            float* Cf = (float*)Cv;
            float4 z = make_float4(0.f, 0.f, 0.f, 0.f);
            for (int i = t; i < 128 * 32; i += 256) {
                int r = i >> 5, c4 = (i & 31) * 4;
                *(float4*)&Cf[(size_t)(bm * 128 + r) * N + bn * 128 + c4] = z;
            }
            return;
        }
    }

    __shared__ __align__(16) __half sA[128][40];
    __shared__ __align__(16) __half sB[32][136];

    float acc[2][8][4];
#pragma unroll
    for (int mi = 0; mi < 2; mi++)
#pragma unroll
        for (int ni = 0; ni < 8; ni++)
#pragma unroll
            for (int j = 0; j < 4; j++) acc[mi][ni][j] = 0.f;

    const float* A32 = (const float*)Av;
    const __half* A16 = (const __half*)Av;

    const int arow = t >> 3, ac = (t & 7) * 4;
    const int brow = t >> 4, bc = (t & 15) * 8;
    const int li = lane & 15;
    const int nk = K / 32;

    for (int kt = 0; kt < nk; kt++) {
        float4 af[4];
        uint2 ah[4];
        uint4 bf[2];
        if (A_F32) {
#pragma unroll
            for (int p = 0; p < 4; p++)
                af[p] = *(const float4*)(A32 + (size_t)(bm * 128 + arow + 32 * p) * K + kt * 32 + ac);
        } else {
#pragma unroll
            for (int p = 0; p < 4; p++)
                ah[p] = *(const uint2*)(A16 + (size_t)(bm * 128 + arow + 32 * p) * K + kt * 32 + ac);
        }
#pragma unroll
        for (int p = 0; p < 2; p++)
            bf[p] = *(const uint4*)(Bw + (size_t)(kt * 32 + brow + 16 * p) * N + bn * 128 + bc);

        __syncthreads();
        if (A_F32) {
#pragma unroll
            for (int p = 0; p < 4; p++) {
                __half2 h01 = __floats2half2_rn(af[p].x, af[p].y);
                __half2 h23 = __floats2half2_rn(af[p].z, af[p].w);
                uint2 u;
                u.x = h2_as_u32(h01);
                u.y = h2_as_u32(h23);
                *(uint2*)&sA[arow + 32 * p][ac] = u;
            }
        } else {
#pragma unroll
            for (int p = 0; p < 4; p++) *(uint2*)&sA[arow + 32 * p][ac] = ah[p];
        }
#pragma unroll
        for (int p = 0; p < 2; p++) *(uint4*)&sB[brow + 16 * p][bc] = bf[p];
        __syncthreads();

#pragma unroll
        for (int kk = 0; kk < 2; kk++) {
            uint32_t a[2][4];
#pragma unroll
            for (int mi = 0; mi < 2; mi++)
                ldsm_x4(a[mi], &sA[wm * 32 + mi * 16 + li][kk * 16 + ((lane >> 4) << 3)]);
#pragma unroll
            for (int ni = 0; ni < 8; ni++) {
                uint32_t bb[2];
                ldsm_x2_t(bb, &sB[kk * 16 + li][wn * 64 + ni * 8]);
                mma16816(acc[0][ni], a[0], bb);
                mma16816(acc[1][ni], a[1], bb);
            }
        }
    }

    // epilogue
    const int row_base = bm * 128 + wm * 32;
    const int col_base = bn * 128 + wn * 64;
    if (C_F32) {
        float* Cf = (float*)Cv;
#pragma unroll
        for (int mi = 0; mi < 2; mi++) {
#pragma unroll
            for (int ni = 0; ni < 8; ni++) {
                int r = row_base + mi * 16 + (lane >> 2);
                int c = col_base + ni * 8 + (lane & 3) * 2;
                float b0 = BIAS ? bias[c] : 0.f;
                float b1 = BIAS ? bias[c + 1] : 0.f;
                bool v0 = !GATE_ZERO || ((r & (L_ - 1)) < slen_blk);
                bool v1 = !GATE_ZERO || (((r + 8) & (L_ - 1)) < slen_blk);
                float2 o0 = v0 ? make_float2(acc[mi][ni][0] + b0, acc[mi][ni][1] + b1)
                               : make_float2(0.f, 0.f);
                float2 o1 = v1 ? make_float2(acc[mi][ni][2] + b0, acc[mi][ni][3] + b1)
                               : make_float2(0.f, 0.f);
                *(float2*)&Cf[(size_t)r * N + c] = o0;
                *(float2*)&Cf[(size_t)(r + 8) * N + c] = o1;
            }
        }
    } else {
        __half* Ch = (__half*)Cv;
#pragma unroll
        for (int mi = 0; mi < 2; mi++) {
#pragma unroll
            for (int ni = 0; ni < 8; ni++) {
                int r = row_base + mi * 16 + (lane >> 2);
                int c = col_base + ni * 8 + (lane & 3) * 2;
                *(__half2*)(Ch + (size_t)r * N + c) =
                    __floats2half2_rn(acc[mi][ni][0], acc[mi][ni][1]);
                *(__half2*)(Ch + (size_t)(r + 8) * N + c) =
                    __floats2half2_rn(acc[mi][ni][2], acc[mi][ni][3]);
            }
        }
    }
}

// ---------------- fused flash attention over full context ----------------
// grid (L/128, H, B); 256 threads = 8 warps; warp owns 16 query rows.
// S processed in 8 chunks of 64 with online softmax; fp32 stats/accum, fp16 mma.
__global__ void __launch_bounds__(256)
attn_kernel(const int* __restrict__ seq) {
    const int b = blockIdx.z, h = blockIdx.y;
    const int l0 = blockIdx.x * 128;
    if (l0 >= seq[b]) return;

    __shared__ __align__(16) __half sQ[128][72];
    __shared__ __align__(16) __half sK[64][72];
    __shared__ __align__(16) __half sV[64][72];

    const int t = threadIdx.x, lane = t & 31, w = t >> 5;
    const int li = lane & 15;

    // load Q tile [128 x 64]
    {
        int row = t >> 3, c8 = (t & 7) * 8;
#pragma unroll
        for (int p = 0; p < 4; p++) {
            *(uint4*)&sQ[row + 32 * p][c8] =
                *(const uint4*)(g_q + ((size_t)b * L_ + l0 + row + 32 * p) * IN_ + h * 64 + c8);
        }
    }
    __syncthreads();

    // Q fragments (held across all chunks): 4 k-steps x 4 regs
    uint32_t aq[4][4];
#pragma unroll
    for (int ks = 0; ks < 4; ks++)
        ldsm_x4(aq[ks], &sQ[w * 16 + li][ks * 16 + ((lane >> 4) << 3)]);

    float m0 = -1e30f, m1 = -1e30f, ls0 = 0.f, ls1 = 0.f;
    float oa[8][4];
#pragma unroll
    for (int nd = 0; nd < 8; nd++)
#pragma unroll
        for (int j = 0; j < 4; j++) oa[nd][j] = 0.f;

    for (int sc = 0; sc < 8; sc++) {
        __syncthreads();
        {
            int row = t >> 3, c8 = (t & 7) * 8;
#pragma unroll
            for (int p = 0; p < 2; p++) {
                size_t gi = ((size_t)b * S_ + sc * 64 + row + 32 * p) * IN_ + h * 64 + c8;
                *(uint4*)&sK[row + 32 * p][c8] = *(const uint4*)(g_k + gi);
                *(uint4*)&sV[row + 32 * p][c8] = *(const uint4*)(g_v + gi);
            }
        }
        __syncthreads();

        // scores = Q @ K^T, 16 x 64 per warp
        float sacc[8][4];
#pragma unroll
        for (int ni = 0; ni < 8; ni++)
#pragma unroll
            for (int j = 0; j < 4; j++) sacc[ni][j] = 0.f;
#pragma unroll
        for (int ni = 0; ni < 8; ni++) {
#pragma unroll
            for (int ks = 0; ks < 4; ks++) {
                uint32_t bb[2];
                ldsm_x2(bb, &sK[ni * 8 + (li & 7)][ks * 16 + (li & 8)]);
                mma16816(sacc[ni], aq[ks], bb);
            }
        }

        // scale + online softmax
        float mx0 = -1e30f, mx1 = -1e30f;
#pragma unroll
        for (int ni = 0; ni < 8; ni++) {
#pragma unroll
            for (int j = 0; j < 4; j++) sacc[ni][j] *= 0.125f;
            mx0 = fmaxf(mx0, fmaxf(sacc[ni][0], sacc[ni][1]));
            mx1 = fmaxf(mx1, fmaxf(sacc[ni][2], sacc[ni][3]));
        }
        mx0 = fmaxf(mx0, __shfl_xor_sync(0xffffffffu, mx0, 1));
        mx0 = fmaxf(mx0, __shfl_xor_sync(0xffffffffu, mx0, 2));
        mx1 = fmaxf(mx1, __shfl_xor_sync(0xffffffffu, mx1, 1));
        mx1 = fmaxf(mx1, __shfl_xor_sync(0xffffffffu, mx1, 2));
        float nm0 = fmaxf(m0, mx0), nm1 = fmaxf(m1, mx1);
        float al0 = __expf(m0 - nm0), al1 = __expf(m1 - nm1);

        float s0 = 0.f, s1 = 0.f;
        uint32_t pp[16];
#pragma unroll
        for (int ni = 0; ni < 8; ni++) {
            float p0 = __expf(sacc[ni][0] - nm0);
            float p1 = __expf(sacc[ni][1] - nm0);
            float p2 = __expf(sacc[ni][2] - nm1);
            float p3 = __expf(sacc[ni][3] - nm1);
            s0 += p0 + p1;
            s1 += p2 + p3;
            pp[ni * 2]     = h2_as_u32(__floats2half2_rn(p0, p1));
            pp[ni * 2 + 1] = h2_as_u32(__floats2half2_rn(p2, p3));
        }
        s0 += __shfl_xor_sync(0xffffffffu, s0, 1);
        s0 += __shfl_xor_sync(0xffffffffu, s0, 2);
        s1 += __shfl_xor_sync(0xffffffffu, s1, 1);
        s1 += __shfl_xor_sync(0xffffffffu, s1, 2);
        ls0 = ls0 * al0 + s0;
        ls1 = ls1 * al1 + s1;
        m0 = nm0;
        m1 = nm1;
#pragma unroll
        for (int nd = 0; nd < 8; nd++) {
            oa[nd][0] *= al0;
            oa[nd][1] *= al0;
            oa[nd][2] *= al1;
            oa[nd][3] *= al1;
        }

        // O += P @ V  (P fragments reused straight from score registers)
#pragma unroll
        for (int kk = 0; kk < 4; kk++) {
#pragma unroll
            for (int nd = 0; nd < 8; nd++) {
                uint32_t bv[2];
                ldsm_x2_t(bv, &sV[kk * 16 + li][nd * 8]);
                mma16816(oa[nd], &pp[kk * 4], bv);
            }
        }
    }

    // epilogue: normalize + store fp16 to g_o
    float inv0 = __fdividef(1.f, ls0);
    float inv1 = __fdividef(1.f, ls1);
    int r = l0 + w * 16 + (lane >> 2);
    size_t base0 = ((size_t)b * L_ + r) * IN_ + h * 64 + (lane & 3) * 2;
    size_t base1 = base0 + (size_t)8 * IN_;
#pragma unroll
    for (int nd = 0; nd < 8; nd++) {
        *(__half2*)(g_o + base0 + nd * 8) = __floats2half2_rn(oa[nd][0] * inv0, oa[nd][1] * inv0);
        *(__half2*)(g_o + base1 + nd * 8) = __floats2half2_rn(oa[nd][2] * inv1, oa[nd][3] * inv1);
    }
}

// ---------------- launch ----------------
extern "C" void kernel_launch(void* const* d_in, const int* in_sizes, int n_in,
                              void* d_out, int out_size) {
    const float* x   = (const float*)d_in[0];
    const float* ctx = (const float*)d_in[1];
    const int*   seq = (const int*)d_in[2];
    const float* Wq  = (const float*)d_in[3];
    const float* Wk  = (const float*)d_in[4];
    const float* Wv  = (const float*)d_in[5];
    const float* Wo  = (const float*)d_in[6];
    const float* bo  = (const float*)d_in[7];
    float* out = (float*)d_out;

    void *pWq, *pWk, *pWv, *pWo, *pQ, *pK, *pV, *pO;
    cudaGetSymbolAddress(&pWq, g_Wq);
    cudaGetSymbolAddress(&pWk, g_Wk);
    cudaGetSymbolAddress(&pWv, g_Wv);
    cudaGetSymbolAddress(&pWo, g_Wo);
    cudaGetSymbolAddress(&pQ, g_q);
    cudaGetSymbolAddress(&pK, g_k);
    cudaGetSymbolAddress(&pV, g_v);
    cudaGetSymbolAddress(&pO, g_o);

    // 1. convert weights to fp16
    f2h_kernel<<<(DQ_ * IN_ + 255) / 256, 256>>>(Wq, (__half*)pWq, DQ_ * IN_);
    f2h_kernel<<<(DC_ * IN_ + 255) / 256, 256>>>(Wk, (__half*)pWk, DC_ * IN_);
    f2h_kernel<<<(DC_ * IN_ + 255) / 256, 256>>>(Wv, (__half*)pWv, DC_ * IN_);
    f2h_kernel<<<(IN_ * DQ_ + 255) / 256, 256>>>(Wo, (__half*)pWo, IN_ * DQ_);

    // 2. K / V projections: [B*S, DC] @ [DC, IN]
    gemm_mma<true, false, false, false, false>
        <<<dim3(IN_ / 128, (B_ * S_) / 128), 256>>>(ctx, (const __half*)pWk, pK,
                                                    B_ * S_, IN_, DC_, nullptr, nullptr);
    gemm_mma<true, false, false, false, false>
        <<<dim3(IN_ / 128, (B_ * S_) / 128), 256>>>(ctx, (const __half*)pWv, pV,
                                                    B_ * S_, IN_, DC_, nullptr, nullptr);

    // 3. Q projection (skip fully-invalid row tiles): [B*L, DQ] @ [DQ, IN]
    gemm_mma<true, false, true, false, false>
        <<<dim3(IN_ / 128, (B_ * L_) / 128), 256>>>(x, (const __half*)pWq, pQ,
                                                    B_ * L_, IN_, DQ_, seq, nullptr);

    // 4. fused attention
    attn_kernel<<<dim3(L_ / 128, H_, B_), 256>>>(seq);

    // 5. output projection + bias + seq_len zero-gating: [B*L, IN] @ [IN, DQ]
    gemm_mma<false, true, false, true, true>
        <<<dim3(DQ_ / 128, (B_ * L_) / 128), 256>>>(pO, (const __half*)pWo, out,
                                                    B_ * L_, DQ_, IN_, seq, bo);
}

// round 4
// speedup vs baseline: 1.2945x; 1.2945x over previous
#include <cuda_runtime.h>
#include <cuda_fp16.h>
#include <cstdint>

// Problem constants
static constexpr int B_  = 8;
static constexpr int L_  = 8192;
static constexpr int S_  = 512;
static constexpr int DQ_ = 256;
static constexpr int DC_ = 768;
static constexpr int H_  = 8;
static constexpr int IN_ = 512;   // H*DH
static constexpr int LOG2L = 13;  // log2(L_)

// ---------------- static device scratch (no allocations allowed) ----------------
__device__ __half g_Wq[DQ_ * IN_];
__device__ __half g_Wkv[DC_ * 1024];          // [DC][ Wk(512) | Wv(512) ]
__device__ __half g_Wo[IN_ * DQ_];
__device__ __half g_q[(size_t)B_ * L_ * IN_];
__device__ __half g_kv[(size_t)B_ * S_ * 1024]; // [B*S][ K(512) | V(512) ]
__device__ __half g_o[(size_t)B_ * L_ * IN_];

// ---------------- small helpers ----------------
__device__ __forceinline__ uint32_t smem_u32(const void* p) {
    return (uint32_t)__cvta_generic_to_shared(p);
}
__device__ __forceinline__ void ldsm_x4(uint32_t* r, const void* p) {
    uint32_t a = smem_u32(p);
    asm volatile("ldmatrix.sync.aligned.m8n8.x4.shared.b16 {%0,%1,%2,%3}, [%4];"
                 : "=r"(r[0]), "=r"(r[1]), "=r"(r[2]), "=r"(r[3]) : "r"(a));
}
__device__ __forceinline__ void ldsm_x2(uint32_t* r, const void* p) {
    uint32_t a = smem_u32(p);
    asm volatile("ldmatrix.sync.aligned.m8n8.x2.shared.b16 {%0,%1}, [%2];"
                 : "=r"(r[0]), "=r"(r[1]) : "r"(a));
}
__device__ __forceinline__ void ldsm_x2_t(uint32_t* r, const void* p) {
    uint32_t a = smem_u32(p);
    asm volatile("ldmatrix.sync.aligned.m8n8.x2.trans.shared.b16 {%0,%1}, [%2];"
                 : "=r"(r[0]), "=r"(r[1]) : "r"(a));
}
__device__ __forceinline__ void mma16816(float* c, const uint32_t* a, const uint32_t* b) {
    asm volatile(
        "mma.sync.aligned.m16n8k16.row.col.f32.f16.f16.f32 "
        "{%0,%1,%2,%3}, {%4,%5,%6,%7}, {%8,%9}, {%0,%1,%2,%3};"
        : "+f"(c[0]), "+f"(c[1]), "+f"(c[2]), "+f"(c[3])
        : "r"(a[0]), "r"(a[1]), "r"(a[2]), "r"(a[3]), "r"(b[0]), "r"(b[1]));
}
__device__ __forceinline__ uint32_t h2_as_u32(__half2 h) {
    return *reinterpret_cast<uint32_t*>(&h);
}
__device__ __forceinline__ float ex2(float x) {
    float y;
    asm("ex2.approx.ftz.f32 %0, %1;" : "=f"(y) : "f"(x));
    return y;
}
__device__ __forceinline__ void cp_async16(uint32_t dst, const void* src) {
    asm volatile("cp.async.cg.shared.global [%0], [%1], 16;\n" :: "r"(dst), "l"(src));
}
__device__ __forceinline__ void cp_commit() {
    asm volatile("cp.async.commit_group;\n" ::: "memory");
}
__device__ __forceinline__ void cp_wait0() {
    asm volatile("cp.async.wait_group 0;\n" ::: "memory");
}

// ---------------- fused weight conversion (one launch) ----------------
// Wk/Wv interleave into g_Wkv: [DC][0:512)=Wk, [512:1024)=Wv.
__global__ void f2h_all(const float* __restrict__ Wq, const float* __restrict__ Wk,
                        const float* __restrict__ Wv, const float* __restrict__ Wo,
                        __half* __restrict__ dWq, __half* __restrict__ dWkv,
                        __half* __restrict__ dWo) {
    const int NQ = DQ_ * IN_ / 4;   // 32768 vec4
    const int NK = DC_ * IN_ / 4;   // 98304 vec4
    int i = blockIdx.x * 256 + threadIdx.x;
    float4 v;
    __half* dst;
    if (i < NQ) {
        v = ((const float4*)Wq)[i];
        dst = dWq + i * 4;
    } else if (i < NQ + NK) {
        int j = i - NQ;
        v = ((const float4*)Wk)[j];
        int j4 = j * 4;
        dst = dWkv + (j4 >> 9) * 1024 + (j4 & 511);
    } else if (i < NQ + 2 * NK) {
        int j = i - NQ - NK;
        v = ((const float4*)Wv)[j];
        int j4 = j * 4;
        dst = dWkv + (j4 >> 9) * 1024 + 512 + (j4 & 511);
    } else {
        int j = i - NQ - 2 * NK;
        v = ((const float4*)Wo)[j];
        dst = dWo + j * 4;
    }
    __half2* d2 = (__half2*)dst;
    d2[0] = __floats2half2_rn(v.x, v.y);
    d2[1] = __floats2half2_rn(v.z, v.w);
}

// ---------------- pipelined tiled GEMM: C[M,N] = A[M,K] @ B[K,N] -------------
// Depth-2 pipeline: A via register prefetch (+f32->f16 convert), B via cp.async,
// double-buffered smem, one __syncthreads per k-iter.
// BM=128, BN=128, BK=32, 256 threads = 8 warps (4m x 2n), warp tile 32x64.
template <bool A_F32, bool C_F32, bool GATE_SKIP, bool GATE_ZERO, bool BIAS>
__global__ void __launch_bounds__(256)
gemm_mma(const void* __restrict__ Av, const __half* __restrict__ Bw, void* __restrict__ Cv,
         int M, int N, int K, const int* __restrict__ seq, const float* __restrict__ bias) {
    const int bn = blockIdx.x, bm = blockIdx.y;
    const int t = threadIdx.x, lane = t & 31, w = t >> 5;
    const int wm = w & 3, wn = w >> 2;

    if (GATE_SKIP) {
        int r0 = bm * 128;
        if ((r0 & (L_ - 1)) >= seq[r0 >> LOG2L]) return;
    }
    int slen_blk = 0;
    if (GATE_ZERO) {
        int r0 = bm * 128;
        slen_blk = seq[r0 >> LOG2L];
        if ((r0 & (L_ - 1)) >= slen_blk) {
            float* Cf = (float*)Cv;
            float4 z = make_float4(0.f, 0.f, 0.f, 0.f);
            for (int i = t; i < 128 * (128 / 4); i += 256) {
                int r = i / (128 / 4), c4 = (i % (128 / 4)) * 4;
                *(float4*)&Cf[(size_t)(bm * 128 + r) * N + bn * 128 + c4] = z;
            }
            return;
        }
    }

    __shared__ __align__(16) __half sA[2][128][40];
    __shared__ __align__(16) __half sB[2][32][136];

    float acc[2][8][4];
#pragma unroll
    for (int mi = 0; mi < 2; mi++)
#pragma unroll
        for (int ni = 0; ni < 8; ni++)
#pragma unroll
            for (int j = 0; j < 4; j++) acc[mi][ni][j] = 0.f;

    const float* A32 = (const float*)Av;
    const __half* A16 = (const __half*)Av;

    const int arow = t >> 3, ac = (t & 7) * 4;
    const int brow = t >> 4, bc = (t & 15) * 8;
    const int li = lane & 15;
    const int nk = K / 32;

    float4 af[4];
    uint2 ah[4];

    // ---- prologue: tile 0 ----
    if (A_F32) {
#pragma unroll
        for (int p = 0; p < 4; p++)
            af[p] = *(const float4*)(A32 + (size_t)(bm * 128 + arow + 32 * p) * K + ac);
    } else {
#pragma unroll
        for (int p = 0; p < 4; p++)
            ah[p] = *(const uint2*)(A16 + (size_t)(bm * 128 + arow + 32 * p) * K + ac);
    }
#pragma unroll
    for (int p = 0; p < 2; p++)
        cp_async16(smem_u32(&sB[0][brow + 16 * p][bc]),
                   Bw + (size_t)(brow + 16 * p) * N + bn * 128 + bc);
    cp_commit();
    if (A_F32) {
#pragma unroll
        for (int p = 0; p < 4; p++) {
            uint2 u;
            u.x = h2_as_u32(__floats2half2_rn(af[p].x, af[p].y));
            u.y = h2_as_u32(__floats2half2_rn(af[p].z, af[p].w));
            *(uint2*)&sA[0][arow + 32 * p][ac] = u;
        }
    } else {
#pragma unroll
        for (int p = 0; p < 4; p++) *(uint2*)&sA[0][arow + 32 * p][ac] = ah[p];
    }
    cp_wait0();
    __syncthreads();

    for (int kt = 0; kt < nk; kt++) {
        const int cur = kt & 1, nxt = cur ^ 1;
        const bool more = (kt + 1 < nk);
        if (more) {
            // prefetch tile kt+1: A -> regs, B -> cp.async into other buffer
            if (A_F32) {
#pragma unroll
                for (int p = 0; p < 4; p++)
                    af[p] = *(const float4*)(A32 + (size_t)(bm * 128 + arow + 32 * p) * K +
                                             (kt + 1) * 32 + ac);
            } else {
#pragma unroll
                for (int p = 0; p < 4; p++)
                    ah[p] = *(const uint2*)(A16 + (size_t)(bm * 128 + arow + 32 * p) * K +
                                            (kt + 1) * 32 + ac);
            }
#pragma unroll
            for (int p = 0; p < 2; p++)
                cp_async16(smem_u32(&sB[nxt][brow + 16 * p][bc]),
                           Bw + (size_t)((kt + 1) * 32 + brow + 16 * p) * N + bn * 128 + bc);
            cp_commit();
        }

        // compute tile kt
#pragma unroll
        for (int kk = 0; kk < 2; kk++) {
            uint32_t a[2][4];
#pragma unroll
            for (int mi = 0; mi < 2; mi++)
                ldsm_x4(a[mi], &sA[cur][wm * 32 + mi * 16 + li][kk * 16 + ((lane >> 4) << 3)]);
#pragma unroll
            for (int ni = 0; ni < 8; ni++) {
                uint32_t bb[2];
                ldsm_x2_t(bb, &sB[cur][kk * 16 + li][wn * 64 + ni * 8]);
                mma16816(acc[0][ni], a[0], bb);
                mma16816(acc[1][ni], a[1], bb);
            }
        }

        if (more) {
            if (A_F32) {
#pragma unroll
                for (int p = 0; p < 4; p++) {
                    uint2 u;
                    u.x = h2_as_u32(__floats2half2_rn(af[p].x, af[p].y));
                    u.y = h2_as_u32(__floats2half2_rn(af[p].z, af[p].w));
                    *(uint2*)&sA[nxt][arow + 32 * p][ac] = u;
                }
            } else {
#pragma unroll
                for (int p = 0; p < 4; p++) *(uint2*)&sA[nxt][arow + 32 * p][ac] = ah[p];
            }
            cp_wait0();
            __syncthreads();
        }
    }

    // epilogue
    const int row_base = bm * 128 + wm * 32;
    const int col_base = bn * 128 + wn * 64;
    if (C_F32) {
        float* Cf = (float*)Cv;
#pragma unroll
        for (int mi = 0; mi < 2; mi++) {
#pragma unroll
            for (int ni = 0; ni < 8; ni++) {
                int r = row_base + mi * 16 + (lane >> 2);
                int c = col_base + ni * 8 + (lane & 3) * 2;
                float b0 = BIAS ? bias[c] : 0.f;
                float b1 = BIAS ? bias[c + 1] : 0.f;
                bool v0 = !GATE_ZERO || ((r & (L_ - 1)) < slen_blk);
                bool v1 = !GATE_ZERO || (((r + 8) & (L_ - 1)) < slen_blk);
                float2 o0 = v0 ? make_float2(acc[mi][ni][0] + b0, acc[mi][ni][1] + b1)
                               : make_float2(0.f, 0.f);
                float2 o1 = v1 ? make_float2(acc[mi][ni][2] + b0, acc[mi][ni][3] + b1)
                               : make_float2(0.f, 0.f);
                *(float2*)&Cf[(size_t)r * N + c] = o0;
                *(float2*)&Cf[(size_t)(r + 8) * N + c] = o1;
            }
        }
    } else {
        __half* Ch = (__half*)Cv;
#pragma unroll
        for (int mi = 0; mi < 2; mi++) {
#pragma unroll
            for (int ni = 0; ni < 8; ni++) {
                int r = row_base + mi * 16 + (lane >> 2);
                int c = col_base + ni * 8 + (lane & 3) * 2;
                *(__half2*)(Ch + (size_t)r * N + c) =
                    __floats2half2_rn(acc[mi][ni][0], acc[mi][ni][1]);
                *(__half2*)(Ch + (size_t)(r + 8) * N + c) =
                    __floats2half2_rn(acc[mi][ni][2], acc[mi][ni][3]);
            }
        }
    }
}

// ---------------- fused flash attention over full context ----------------
// grid (L/128, H, B); 256 threads = 8 warps; warp owns 16 query rows.
// S in 8 chunks of 64, cp.async double-buffered K/V, online softmax in log2 domain.
// Smem trick: the 128x72 Q staging tile is dead after fragment extraction and is
// exactly one KV buffer (2*64*72 halves), so KV buf1 aliases it. Total smem 36 KB.
__global__ void __launch_bounds__(256)
attn_kernel(const int* __restrict__ seq) {
    const int b = blockIdx.z, h = blockIdx.y;
    const int l0 = blockIdx.x * 128;
    if (l0 >= seq[b]) return;

    __shared__ __align__(16) __half sBuf0[2][64][72];  // KV buf0: [K/V][row][col]
    __shared__ __align__(16) __half sBuf1[2][64][72];  // Q staging, then KV buf1

    const int t = threadIdx.x, lane = t & 31, w = t >> 5;
    const int li = lane & 15;

    // cp.async K/V chunk loader geometry: 4 threads per row, 2 segs each per array
    const int kvr = t >> 2;        // 0..63
    const int kvs = t & 3;         // base segment (of 8 x 16B per 128B row)
    const size_t kv_row0 = (size_t)b * S_ * 1024 + (size_t)kvr * 1024 + h * 64;

    // issue chunk 0 into buf0
    {
#pragma unroll
        for (int p = 0; p < 2; p++) {
            int seg = kvs + 4 * p;
            cp_async16(smem_u32(&sBuf0[0][kvr][seg * 8]), g_kv + kv_row0 + seg * 8);
            cp_async16(smem_u32(&sBuf0[1][kvr][seg * 8]), g_kv + kv_row0 + 512 + seg * 8);
        }
        cp_commit();
    }

    // load Q tile [128 x 64] into the buf1 region (viewed as 128 rows x 72)
    __half(*sQ)[72] = reinterpret_cast<__half(*)[72]>(sBuf1);
    {
        int row = t >> 3, c8 = (t & 7) * 8;
#pragma unroll
        for (int p = 0; p < 4; p++) {
            *(uint4*)&sQ[row + 32 * p][c8] =
                *(const uint4*)(g_q + ((size_t)b * L_ + l0 + row + 32 * p) * IN_ + h * 64 + c8);
        }
    }
    cp_wait0();
    __syncthreads();

    // Q fragments (held across all chunks)
    uint32_t aq[4][4];
#pragma unroll
    for (int ks = 0; ks < 4; ks++)
        ldsm_x4(aq[ks], &sQ[w * 16 + li][ks * 16 + ((lane >> 4) << 3)]);
    __syncthreads();   // everyone done reading Q before buf1 is reused for KV

    // softmax state in log2 domain: scores pre-scaled by (1/sqrt(DH)) * log2(e)
    const float kScale = 0.125f * 1.44269504088896f;
    float m0 = -1e30f, m1 = -1e30f, ls0 = 0.f, ls1 = 0.f;
    float oa[8][4];
#pragma unroll
    for (int nd = 0; nd < 8; nd++)
#pragma unroll
        for (int j = 0; j < 4; j++) oa[nd][j] = 0.f;

    for (int sc = 0; sc < 8; sc++) {
        const int cur = sc & 1;
        if (sc < 7) {
            __half(*dst)[64][72] = (cur ? sBuf0 : sBuf1);
            size_t rowb = kv_row0 + (size_t)(sc + 1) * 64 * 1024;
#pragma unroll
            for (int p = 0; p < 2; p++) {
                int seg = kvs + 4 * p;
                cp_async16(smem_u32(&dst[0][kvr][seg * 8]), g_kv + rowb + seg * 8);
                cp_async16(smem_u32(&dst[1][kvr][seg * 8]), g_kv + rowb + 512 + seg * 8);
            }
            cp_commit();
        }

        const __half(*sK)[72] = (cur ? sBuf1[0] : sBuf0[0]);
        const __half(*sV)[72] = (cur ? sBuf1[1] : sBuf0[1]);

        // scores = Q @ K^T, 16 x 64 per warp
        float sacc[8][4];
#pragma unroll
        for (int ni = 0; ni < 8; ni++)
#pragma unroll
            for (int j = 0; j < 4; j++) sacc[ni][j] = 0.f;
#pragma unroll
        for (int ni = 0; ni < 8; ni++) {
#pragma unroll
            for (int ks = 0; ks < 4; ks++) {
                uint32_t bb[2];
                ldsm_x2(bb, &sK[ni * 8 + (li & 7)][ks * 16 + (li & 8)]);
                mma16816(sacc[ni], aq[ks], bb);
            }
        }

        // scale into log2 domain + online softmax
        float mx0 = -1e30f, mx1 = -1e30f;
#pragma unroll
        for (int ni = 0; ni < 8; ni++) {
#pragma unroll
            for (int j = 0; j < 4; j++) sacc[ni][j] *= kScale;
            mx0 = fmaxf(mx0, fmaxf(sacc[ni][0], sacc[ni][1]));
            mx1 = fmaxf(mx1, fmaxf(sacc[ni][2], sacc[ni][3]));
        }
        mx0 = fmaxf(mx0, __shfl_xor_sync(0xffffffffu, mx0, 1));
        mx0 = fmaxf(mx0, __shfl_xor_sync(0xffffffffu, mx0, 2));
        mx1 = fmaxf(mx1, __shfl_xor_sync(0xffffffffu, mx1, 1));
        mx1 = fmaxf(mx1, __shfl_xor_sync(0xffffffffu, mx1, 2));
        float nm0 = fmaxf(m0, mx0), nm1 = fmaxf(m1, mx1);
        float al0 = ex2(m0 - nm0), al1 = ex2(m1 - nm1);

        float s0 = 0.f, s1 = 0.f;
        uint32_t pp[16];
#pragma unroll
        for (int ni = 0; ni < 8; ni++) {
            float p0 = ex2(sacc[ni][0] - nm0);
            float p1 = ex2(sacc[ni][1] - nm0);
            float p2 = ex2(sacc[ni][2] - nm1);
            float p3 = ex2(sacc[ni][3] - nm1);
            s0 += p0 + p1;
            s1 += p2 + p3;
            pp[ni * 2]     = h2_as_u32(__floats2half2_rn(p0, p1));
            pp[ni * 2 + 1] = h2_as_u32(__floats2half2_rn(p2, p3));
        }
        s0 += __shfl_xor_sync(0xffffffffu, s0, 1);
        s0 += __shfl_xor_sync(0xffffffffu, s0, 2);
        s1 += __shfl_xor_sync(0xffffffffu, s1, 1);
        s1 += __shfl_xor_sync(0xffffffffu, s1, 2);
        ls0 = ls0 * al0 + s0;
        ls1 = ls1 * al1 + s1;
        m0 = nm0;
        m1 = nm1;
#pragma unroll
        for (int nd = 0; nd < 8; nd++) {
            oa[nd][0] *= al0;
            oa[nd][1] *= al0;
            oa[nd][2] *= al1;
            oa[nd][3] *= al1;
        }

        // O += P @ V
#pragma unroll
        for (int kk = 0; kk < 4; kk++) {
#pragma unroll
            for (int nd = 0; nd < 8; nd++) {
                uint32_t bv[2];
                ldsm_x2_t(bv, &sV[kk * 16 + li][nd * 8]);
                mma16816(oa[nd], &pp[kk * 4], bv);
            }
        }

        if (sc < 7) {
            cp_wait0();
            __syncthreads();
        }
    }

    // epilogue: normalize + store fp16 to g_o
    float inv0 = __fdividef(1.f, ls0);
    float inv1 = __fdividef(1.f, ls1);
    int r = l0 + w * 16 + (lane >> 2);
    size_t base0 = ((size_t)b * L_ + r) * IN_ + h * 64 + (lane & 3) * 2;
    size_t base1 = base0 + (size_t)8 * IN_;
#pragma unroll
    for (int nd = 0; nd < 8; nd++) {
        *(__half2*)(g_o + base0 + nd * 8) = __floats2half2_rn(oa[nd][0] * inv0, oa[nd][1] * inv0);
        *(__half2*)(g_o + base1 + nd * 8) = __floats2half2_rn(oa[nd][2] * inv1, oa[nd][3] * inv1);
    }
}

// ---------------- launch ----------------
extern "C" void kernel_launch(void* const* d_in, const int* in_sizes, int n_in,
                              void* d_out, int out_size) {
    const float* x   = (const float*)d_in[0];
    const float* ctx = (const float*)d_in[1];
    const int*   seq = (const int*)d_in[2];
    const float* Wq  = (const float*)d_in[3];
    const float* Wk  = (const float*)d_in[4];
    const float* Wv  = (const float*)d_in[5];
    const float* Wo  = (const float*)d_in[6];
    const float* bo  = (const float*)d_in[7];
    float* out = (float*)d_out;

    void *pWq, *pWkv, *pWo, *pQ, *pKV, *pO;
    cudaGetSymbolAddress(&pWq, g_Wq);
    cudaGetSymbolAddress(&pWkv, g_Wkv);
    cudaGetSymbolAddress(&pWo, g_Wo);
    cudaGetSymbolAddress(&pQ, g_q);
    cudaGetSymbolAddress(&pKV, g_kv);
    cudaGetSymbolAddress(&pO, g_o);

    // 1. convert all weights in one launch
    f2h_all<<<1024, 256>>>(Wq, Wk, Wv, Wo, (__half*)pWq, (__half*)pWkv, (__half*)pWo);

    // 2. fused K+V projection: [B*S, DC] @ [DC, 1024] -> g_kv
    gemm_mma<true, false, false, false, false>
        <<<dim3(1024 / 128, (B_ * S_) / 128), 256>>>(ctx, (const __half*)pWkv, pKV,
                                                     B_ * S_, 1024, DC_, nullptr, nullptr);

    // 3. Q projection (skip fully-invalid row tiles): [B*L, DQ] @ [DQ, IN]
    gemm_mma<true, false, true, false, false>
        <<<dim3(IN_ / 128, (B_ * L_) / 128), 256>>>(x, (const __half*)pWq, pQ,
                                                    B_ * L_, IN_, DQ_, seq, nullptr);

    // 4. fused attention
    attn_kernel<<<dim3(L_ / 128, H_, B_), 256>>>(seq);

    // 5. output projection + bias + seq_len zero-gating: [B*L, IN] @ [IN, DQ]
    gemm_mma<false, true, false, true, true>
        <<<dim3(DQ_ / 128, (B_ * L_) / 128), 256>>>(pO, (const __half*)pWo, out,
                                                    B_ * L_, DQ_, IN_, seq, bo);
}

// round 5
// speedup vs baseline: 1.3955x; 1.0780x over previous
#include <cuda_runtime.h>
#include <cuda_fp16.h>
#include <cstdint>

// Problem constants
static constexpr int B_  = 8;
static constexpr int L_  = 8192;
static constexpr int S_  = 512;
static constexpr int DQ_ = 256;
static constexpr int DC_ = 768;
static constexpr int H_  = 8;
static constexpr int IN_ = 512;   // H*DH
static constexpr int LOG2L = 13;  // log2(L_)

// ---------------- static device scratch (no allocations allowed) ----------------
__device__ __half g_Wq[DQ_ * IN_];
__device__ __half g_Wkv[DC_ * 1024];          // [DC][ Wk(512) | Wv(512) ]
__device__ __half g_Wo[IN_ * DQ_];
__device__ __half g_q[(size_t)B_ * L_ * IN_];
__device__ __half g_kv[(size_t)B_ * S_ * 1024]; // [B*S][ K(512) | V(512) ]
__device__ __half g_o[(size_t)B_ * L_ * IN_];

// ---------------- small helpers ----------------
__device__ __forceinline__ uint32_t smem_u32(const void* p) {
    return (uint32_t)__cvta_generic_to_shared(p);
}
__device__ __forceinline__ void ldsm_x4(uint32_t* r, const void* p) {
    uint32_t a = smem_u32(p);
    asm volatile("ldmatrix.sync.aligned.m8n8.x4.shared.b16 {%0,%1,%2,%3}, [%4];"
                 : "=r"(r[0]), "=r"(r[1]), "=r"(r[2]), "=r"(r[3]) : "r"(a));
}
__device__ __forceinline__ void ldsm_x4_t(uint32_t* r, const void* p) {
    uint32_t a = smem_u32(p);
    asm volatile("ldmatrix.sync.aligned.m8n8.x4.trans.shared.b16 {%0,%1,%2,%3}, [%4];"
                 : "=r"(r[0]), "=r"(r[1]), "=r"(r[2]), "=r"(r[3]) : "r"(a));
}
__device__ __forceinline__ void mma16816(float* c, const uint32_t* a, const uint32_t* b) {
    asm volatile(
        "mma.sync.aligned.m16n8k16.row.col.f32.f16.f16.f32 "
        "{%0,%1,%2,%3}, {%4,%5,%6,%7}, {%8,%9}, {%0,%1,%2,%3};"
        : "+f"(c[0]), "+f"(c[1]), "+f"(c[2]), "+f"(c[3])
        : "r"(a[0]), "r"(a[1]), "r"(a[2]), "r"(a[3]), "r"(b[0]), "r"(b[1]));
}
__device__ __forceinline__ uint32_t h2_as_u32(__half2 h) {
    return *reinterpret_cast<uint32_t*>(&h);
}
__device__ __forceinline__ float ex2(float x) {
    float y;
    asm("ex2.approx.ftz.f32 %0, %1;" : "=f"(y) : "f"(x));
    return y;
}
__device__ __forceinline__ void cp_async16(uint32_t dst, const void* src) {
    asm volatile("cp.async.cg.shared.global [%0], [%1], 16;\n" :: "r"(dst), "l"(src));
}
__device__ __forceinline__ void cp_commit() {
    asm volatile("cp.async.commit_group;\n" ::: "memory");
}
__device__ __forceinline__ void cp_wait0() {
    asm volatile("cp.async.wait_group 0;\n" ::: "memory");
}

// ---------------- fused weight conversion (one launch) ----------------
__global__ void f2h_all(const float* __restrict__ Wq, const float* __restrict__ Wk,
                        const float* __restrict__ Wv, const float* __restrict__ Wo,
                        __half* __restrict__ dWq, __half* __restrict__ dWkv,
                        __half* __restrict__ dWo) {
    const int NQ = DQ_ * IN_ / 4;   // 32768 vec4
    const int NK = DC_ * IN_ / 4;   // 98304 vec4
    int i = blockIdx.x * 256 + threadIdx.x;
    float4 v;
    __half* dst;
    if (i < NQ) {
        v = ((const float4*)Wq)[i];
        dst = dWq + i * 4;
    } else if (i < NQ + NK) {
        int j = i - NQ;
        v = ((const float4*)Wk)[j];
        int j4 = j * 4;
        dst = dWkv + (j4 >> 9) * 1024 + (j4 & 511);
    } else if (i < NQ + 2 * NK) {
        int j = i - NQ - NK;
        v = ((const float4*)Wv)[j];
        int j4 = j * 4;
        dst = dWkv + (j4 >> 9) * 1024 + 512 + (j4 & 511);
    } else {
        int j = i - NQ - 2 * NK;
        v = ((const float4*)Wo)[j];
        dst = dWo + j * 4;
    }
    __half2* d2 = (__half2*)dst;
    d2[0] = __floats2half2_rn(v.x, v.y);
    d2[1] = __floats2half2_rn(v.z, v.w);
}

// ---------------- pipelined tiled GEMM: C[M,N] = A[M,K] @ B[K,N] -------------
// Depth-2 pipeline; x4 ldmatrix for B (two n-tiles per load).
// oscale: multiplier applied in the f16-output epilogue (folds softmax scale into Q).
template <bool A_F32, bool C_F32, bool GATE_SKIP, bool GATE_ZERO, bool BIAS>
__global__ void __launch_bounds__(256)
gemm_mma(const void* __restrict__ Av, const __half* __restrict__ Bw, void* __restrict__ Cv,
         int M, int N, int K, const int* __restrict__ seq, const float* __restrict__ bias,
         float oscale) {
    const int bn = blockIdx.x, bm = blockIdx.y;
    const int t = threadIdx.x, lane = t & 31, w = t >> 5;
    const int wm = w & 3, wn = w >> 2;

    if (GATE_SKIP) {
        int r0 = bm * 128;
        if ((r0 & (L_ - 1)) >= seq[r0 >> LOG2L]) return;
    }
    int slen_blk = 0;
    if (GATE_ZERO) {
        int r0 = bm * 128;
        slen_blk = seq[r0 >> LOG2L];
        if ((r0 & (L_ - 1)) >= slen_blk) {
            float* Cf = (float*)Cv;
            float4 z = make_float4(0.f, 0.f, 0.f, 0.f);
            for (int i = t; i < 128 * (128 / 4); i += 256) {
                int r = i / (128 / 4), c4 = (i % (128 / 4)) * 4;
                *(float4*)&Cf[(size_t)(bm * 128 + r) * N + bn * 128 + c4] = z;
            }
            return;
        }
    }

    __shared__ __align__(16) __half sA[2][128][40];
    __shared__ __align__(16) __half sB[2][32][136];

    float acc[2][8][4];
#pragma unroll
    for (int mi = 0; mi < 2; mi++)
#pragma unroll
        for (int ni = 0; ni < 8; ni++)
#pragma unroll
            for (int j = 0; j < 4; j++) acc[mi][ni][j] = 0.f;

    const float* A32 = (const float*)Av;
    const __half* A16 = (const __half*)Av;

    const int arow = t >> 3, ac = (t & 7) * 4;
    const int brow = t >> 4, bc = (t & 15) * 8;
    const int li15 = lane & 15;
    const int hi8 = (lane >> 4) << 3;   // 0 for lanes 0-15, 8 for lanes 16-31
    const int nk = K / 32;

    float4 af[4];
    uint2 ah[4];

    // ---- prologue: tile 0 ----
    if (A_F32) {
#pragma unroll
        for (int p = 0; p < 4; p++)
            af[p] = *(const float4*)(A32 + (size_t)(bm * 128 + arow + 32 * p) * K + ac);
    } else {
#pragma unroll
        for (int p = 0; p < 4; p++)
            ah[p] = *(const uint2*)(A16 + (size_t)(bm * 128 + arow + 32 * p) * K + ac);
    }
#pragma unroll
    for (int p = 0; p < 2; p++)
        cp_async16(smem_u32(&sB[0][brow + 16 * p][bc]),
                   Bw + (size_t)(brow + 16 * p) * N + bn * 128 + bc);
    cp_commit();
    if (A_F32) {
#pragma unroll
        for (int p = 0; p < 4; p++) {
            uint2 u;
            u.x = h2_as_u32(__floats2half2_rn(af[p].x, af[p].y));
            u.y = h2_as_u32(__floats2half2_rn(af[p].z, af[p].w));
            *(uint2*)&sA[0][arow + 32 * p][ac] = u;
        }
    } else {
#pragma unroll
        for (int p = 0; p < 4; p++) *(uint2*)&sA[0][arow + 32 * p][ac] = ah[p];
    }
    cp_wait0();
    __syncthreads();

    for (int kt = 0; kt < nk; kt++) {
        const int cur = kt & 1, nxt = cur ^ 1;
        const bool more = (kt + 1 < nk);
        if (more) {
            if (A_F32) {
#pragma unroll
                for (int p = 0; p < 4; p++)
                    af[p] = *(const float4*)(A32 + (size_t)(bm * 128 + arow + 32 * p) * K +
                                             (kt + 1) * 32 + ac);
            } else {
#pragma unroll
                for (int p = 0; p < 4; p++)
                    ah[p] = *(const uint2*)(A16 + (size_t)(bm * 128 + arow + 32 * p) * K +
                                            (kt + 1) * 32 + ac);
            }
#pragma unroll
            for (int p = 0; p < 2; p++)
                cp_async16(smem_u32(&sB[nxt][brow + 16 * p][bc]),
                           Bw + (size_t)((kt + 1) * 32 + brow + 16 * p) * N + bn * 128 + bc);
            cp_commit();
        }

        // compute tile kt (x4 B loads: two n8 tiles per ldmatrix)
#pragma unroll
        for (int kk = 0; kk < 2; kk++) {
            uint32_t a[2][4];
#pragma unroll
            for (int mi = 0; mi < 2; mi++)
                ldsm_x4(a[mi], &sA[cur][wm * 32 + mi * 16 + li15][kk * 16 + hi8]);
#pragma unroll
            for (int p = 0; p < 4; p++) {
                uint32_t bb[4];
                ldsm_x4_t(bb, &sB[cur][kk * 16 + li15][wn * 64 + p * 16 + hi8]);
                mma16816(acc[0][2 * p], a[0], bb);
                mma16816(acc[0][2 * p + 1], a[0], bb + 2);
                mma16816(acc[1][2 * p], a[1], bb);
                mma16816(acc[1][2 * p + 1], a[1], bb + 2);
            }
        }

        if (more) {
            if (A_F32) {
#pragma unroll
                for (int p = 0; p < 4; p++) {
                    uint2 u;
                    u.x = h2_as_u32(__floats2half2_rn(af[p].x, af[p].y));
                    u.y = h2_as_u32(__floats2half2_rn(af[p].z, af[p].w));
                    *(uint2*)&sA[nxt][arow + 32 * p][ac] = u;
                }
            } else {
#pragma unroll
                for (int p = 0; p < 4; p++) *(uint2*)&sA[nxt][arow + 32 * p][ac] = ah[p];
            }
            cp_wait0();
            __syncthreads();
        }
    }

    // epilogue
    const int row_base = bm * 128 + wm * 32;
    const int col_base = bn * 128 + wn * 64;
    if (C_F32) {
        float* Cf = (float*)Cv;
#pragma unroll
        for (int mi = 0; mi < 2; mi++) {
#pragma unroll
            for (int ni = 0; ni < 8; ni++) {
                int r = row_base + mi * 16 + (lane >> 2);
                int c = col_base + ni * 8 + (lane & 3) * 2;
                float b0 = BIAS ? bias[c] : 0.f;
                float b1 = BIAS ? bias[c + 1] : 0.f;
                bool v0 = !GATE_ZERO || ((r & (L_ - 1)) < slen_blk);
                bool v1 = !GATE_ZERO || (((r + 8) & (L_ - 1)) < slen_blk);
                float2 o0 = v0 ? make_float2(acc[mi][ni][0] + b0, acc[mi][ni][1] + b1)
                               : make_float2(0.f, 0.f);
                float2 o1 = v1 ? make_float2(acc[mi][ni][2] + b0, acc[mi][ni][3] + b1)
                               : make_float2(0.f, 0.f);
                *(float2*)&Cf[(size_t)r * N + c] = o0;
                *(float2*)&Cf[(size_t)(r + 8) * N + c] = o1;
            }
        }
    } else {
        __half* Ch = (__half*)Cv;
#pragma unroll
        for (int mi = 0; mi < 2; mi++) {
#pragma unroll
            for (int ni = 0; ni < 8; ni++) {
                int r = row_base + mi * 16 + (lane >> 2);
                int c = col_base + ni * 8 + (lane & 3) * 2;
                *(__half2*)(Ch + (size_t)r * N + c) =
                    __floats2half2_rn(acc[mi][ni][0] * oscale, acc[mi][ni][1] * oscale);
                *(__half2*)(Ch + (size_t)(r + 8) * N + c) =
                    __floats2half2_rn(acc[mi][ni][2] * oscale, acc[mi][ni][3] * oscale);
            }
        }
    }
}

// ---------------- fused flash attention over full context ----------------
// Q in g_q is PRE-SCALED by 0.125*log2(e): scores land directly in log2 domain.
// x4 ldmatrix loads two n-tiles per instruction in both QK^T and PV loops.
__global__ void __launch_bounds__(256)
attn_kernel(const int* __restrict__ seq) {
    const int b = blockIdx.z, h = blockIdx.y;
    const int l0 = blockIdx.x * 128;
    if (l0 >= seq[b]) return;

    __shared__ __align__(16) __half sBuf0[2][64][72];  // KV buf0: [K/V][row][col]
    __shared__ __align__(16) __half sBuf1[2][64][72];  // Q staging, then KV buf1

    const int t = threadIdx.x, lane = t & 31, w = t >> 5;
    const int li15 = lane & 15;
    const int li7 = lane & 7;
    const int c8 = lane & 8;
    const int hi1 = lane >> 4;          // 0/1
    const int hi8 = hi1 << 3;           // 0/8

    // cp.async K/V chunk loader geometry
    const int kvr = t >> 2;
    const int kvs = t & 3;
    const size_t kv_row0 = (size_t)b * S_ * 1024 + (size_t)kvr * 1024 + h * 64;

    // issue chunk 0 into buf0
    {
#pragma unroll
        for (int p = 0; p < 2; p++) {
            int seg = kvs + 4 * p;
            cp_async16(smem_u32(&sBuf0[0][kvr][seg * 8]), g_kv + kv_row0 + seg * 8);
            cp_async16(smem_u32(&sBuf0[1][kvr][seg * 8]), g_kv + kv_row0 + 512 + seg * 8);
        }
        cp_commit();
    }

    // load Q tile [128 x 64] into the buf1 region
    __half(*sQ)[72] = reinterpret_cast<__half(*)[72]>(sBuf1);
    {
        int row = t >> 3, qc = (t & 7) * 8;
#pragma unroll
        for (int p = 0; p < 4; p++) {
            *(uint4*)&sQ[row + 32 * p][qc] =
                *(const uint4*)(g_q + ((size_t)b * L_ + l0 + row + 32 * p) * IN_ + h * 64 + qc);
        }
    }
    cp_wait0();
    __syncthreads();

    uint32_t aq[4][4];
#pragma unroll
    for (int ks = 0; ks < 4; ks++)
        ldsm_x4(aq[ks], &sQ[w * 16 + li15][ks * 16 + hi8]);
    __syncthreads();   // Q fully consumed before buf1 is reused for KV

    float m0 = -1e30f, m1 = -1e30f, ls0 = 0.f, ls1 = 0.f;
    float oa[8][4];
#pragma unroll
    for (int nd = 0; nd < 8; nd++)
#pragma unroll
        for (int j = 0; j < 4; j++) oa[nd][j] = 0.f;

    for (int sc = 0; sc < 8; sc++) {
        const int cur = sc & 1;
        if (sc < 7) {
            __half(*dst)[64][72] = (cur ? sBuf0 : sBuf1);
            size_t rowb = kv_row0 + (size_t)(sc + 1) * 64 * 1024;
#pragma unroll
            for (int p = 0; p < 2; p++) {
                int seg = kvs + 4 * p;
                cp_async16(smem_u32(&dst[0][kvr][seg * 8]), g_kv + rowb + seg * 8);
                cp_async16(smem_u32(&dst[1][kvr][seg * 8]), g_kv + rowb + 512 + seg * 8);
            }
            cp_commit();
        }

        const __half(*sK)[72] = (cur ? sBuf1[0] : sBuf0[0]);
        const __half(*sV)[72] = (cur ? sBuf1[1] : sBuf0[1]);

        // scores = Qs @ K^T (already log2-scaled), 16 x 64 per warp
        float sacc[8][4];
#pragma unroll
        for (int ni = 0; ni < 8; ni++)
#pragma unroll
            for (int j = 0; j < 4; j++) sacc[ni][j] = 0.f;
#pragma unroll
        for (int p = 0; p < 4; p++) {
            // x4: lanes 0-15 -> n-tile 2p, lanes 16-31 -> n-tile 2p+1
            const __half* kaddr = &sK[(2 * p + hi1) * 8 + li7][c8];
#pragma unroll
            for (int ks = 0; ks < 4; ks++) {
                uint32_t bb[4];
                ldsm_x4(bb, kaddr + ks * 16);
                mma16816(sacc[2 * p], aq[ks], bb);
                mma16816(sacc[2 * p + 1], aq[ks], bb + 2);
            }
        }

        // online softmax (log2 domain; no per-element scaling needed)
        float mx0 = -1e30f, mx1 = -1e30f;
#pragma unroll
        for (int ni = 0; ni < 8; ni++) {
            mx0 = fmaxf(mx0, fmaxf(sacc[ni][0], sacc[ni][1]));
            mx1 = fmaxf(mx1, fmaxf(sacc[ni][2], sacc[ni][3]));
        }
        mx0 = fmaxf(mx0, __shfl_xor_sync(0xffffffffu, mx0, 1));
        mx0 = fmaxf(mx0, __shfl_xor_sync(0xffffffffu, mx0, 2));
        mx1 = fmaxf(mx1, __shfl_xor_sync(0xffffffffu, mx1, 1));
        mx1 = fmaxf(mx1, __shfl_xor_sync(0xffffffffu, mx1, 2));
        float nm0 = fmaxf(m0, mx0), nm1 = fmaxf(m1, mx1);
        float al0 = ex2(m0 - nm0), al1 = ex2(m1 - nm1);

        float s0 = 0.f, s1 = 0.f;
        uint32_t pp[16];
#pragma unroll
        for (int ni = 0; ni < 8; ni++) {
            float p0 = ex2(sacc[ni][0] - nm0);
            float p1 = ex2(sacc[ni][1] - nm0);
            float p2 = ex2(sacc[ni][2] - nm1);
            float p3 = ex2(sacc[ni][3] - nm1);
            s0 += p0 + p1;
            s1 += p2 + p3;
            pp[ni * 2]     = h2_as_u32(__floats2half2_rn(p0, p1));
            pp[ni * 2 + 1] = h2_as_u32(__floats2half2_rn(p2, p3));
        }
        s0 += __shfl_xor_sync(0xffffffffu, s0, 1);
        s0 += __shfl_xor_sync(0xffffffffu, s0, 2);
        s1 += __shfl_xor_sync(0xffffffffu, s1, 1);
        s1 += __shfl_xor_sync(0xffffffffu, s1, 2);
        ls0 = ls0 * al0 + s0;
        ls1 = ls1 * al1 + s1;
        m0 = nm0;
        m1 = nm1;
#pragma unroll
        for (int nd = 0; nd < 8; nd++) {
            oa[nd][0] *= al0;
            oa[nd][1] *= al0;
            oa[nd][2] *= al1;
            oa[nd][3] *= al1;
        }

        // O += P @ V (x4 trans: two n8 tiles of V per load)
#pragma unroll
        for (int kk = 0; kk < 4; kk++) {
#pragma unroll
            for (int p = 0; p < 4; p++) {
                uint32_t bv[4];
                ldsm_x4_t(bv, &sV[kk * 16 + li15][p * 16 + hi8]);
                mma16816(oa[2 * p], &pp[kk * 4], bv);
                mma16816(oa[2 * p + 1], &pp[kk * 4], bv + 2);
            }
        }

        if (sc < 7) {
            cp_wait0();
            __syncthreads();
        }
    }

    // epilogue: normalize + store fp16 to g_o
    float inv0 = __fdividef(1.f, ls0);
    float inv1 = __fdividef(1.f, ls1);
    int r = l0 + w * 16 + (lane >> 2);
    size_t base0 = ((size_t)b * L_ + r) * IN_ + h * 64 + (lane & 3) * 2;
    size_t base1 = base0 + (size_t)8 * IN_;
#pragma unroll
    for (int nd = 0; nd < 8; nd++) {
        *(__half2*)(g_o + base0 + nd * 8) = __floats2half2_rn(oa[nd][0] * inv0, oa[nd][1] * inv0);
        *(__half2*)(g_o + base1 + nd * 8) = __floats2half2_rn(oa[nd][2] * inv1, oa[nd][3] * inv1);
    }
}

// ---------------- launch ----------------
extern "C" void kernel_launch(void* const* d_in, const int* in_sizes, int n_in,
                              void* d_out, int out_size) {
    const float* x   = (const float*)d_in[0];
    const float* ctx = (const float*)d_in[1];
    const int*   seq = (const int*)d_in[2];
    const float* Wq  = (const float*)d_in[3];
    const float* Wk  = (const float*)d_in[4];
    const float* Wv  = (const float*)d_in[5];
    const float* Wo  = (const float*)d_in[6];
    const float* bo  = (const float*)d_in[7];
    float* out = (float*)d_out;

    void *pWq, *pWkv, *pWo, *pQ, *pKV, *pO;
    cudaGetSymbolAddress(&pWq, g_Wq);
    cudaGetSymbolAddress(&pWkv, g_Wkv);
    cudaGetSymbolAddress(&pWo, g_Wo);
    cudaGetSymbolAddress(&pQ, g_q);
    cudaGetSymbolAddress(&pKV, g_kv);
    cudaGetSymbolAddress(&pO, g_o);

    const float kQScale = 0.125f * 1.44269504088896f;  // 1/sqrt(DH) * log2(e)

    // 1. convert all weights in one launch
    f2h_all<<<1024, 256>>>(Wq, Wk, Wv, Wo, (__half*)pWq, (__half*)pWkv, (__half*)pWo);

    // 2. fused K+V projection: [B*S, DC] @ [DC, 1024] -> g_kv
    gemm_mma<true, false, false, false, false>
        <<<dim3(1024 / 128, (B_ * S_) / 128), 256>>>(ctx, (const __half*)pWkv, pKV,
                                                     B_ * S_, 1024, DC_, nullptr, nullptr, 1.0f);

    // 3. Q projection, output pre-scaled into log2 softmax domain
    gemm_mma<true, false, true, false, false>
        <<<dim3(IN_ / 128, (B_ * L_) / 128), 256>>>(x, (const __half*)pWq, pQ,
                                                    B_ * L_, IN_, DQ_, seq, nullptr, kQScale);

    // 4. fused attention
    attn_kernel<<<dim3(L_ / 128, H_, B_), 256>>>(seq);

    // 5. output projection + bias + seq_len zero-gating
    gemm_mma<false, true, false, true, true>
        <<<dim3(DQ_ / 128, (B_ * L_) / 128), 256>>>(pO, (const __half*)pWo, out,
                                                    B_ * L_, DQ_, IN_, seq, bo, 1.0f);
}